// round 15
// baseline (speedup 1.0000x reference)
#include <cuda_runtime.h>
#include <cuda_fp16.h>
#include <cstdint>

namespace {
constexpr int B_  = 2;
constexpr int S_  = 2048;
constexpr int D_  = 1024;
constexpr int H_  = 16;
constexpr int DK_ = 64;
}

// Scratch (allocation-free rule: __device__ globals)
__device__ __half g_Qh[B_ * S_ * D_];   // fp16 Q (pre-scaled by log2e/8)
__device__ __half g_Kh[B_ * S_ * D_];
__device__ __half g_Vh[B_ * S_ * D_];
__device__ __half g_Xh[B_ * S_ * D_];   // fp16 attention output
__device__ __half g_Ahq[B_ * S_ * D_];  // fp16 activations
__device__ __half g_Ahk[B_ * S_ * D_];
__device__ __half g_Ahv[B_ * S_ * D_];
__device__ __half g_Whq[D_ * D_];       // fp16 weights
__device__ __half g_Whk[D_ * D_];
__device__ __half g_Whv[D_ * D_];
__device__ __half g_Who[D_ * D_];
__device__ uint32_t g_Mb[(B_ * S_ * S_) / 32];   // bit-packed mask

// Pack two fp32 to one fp16x2 register in a single cvt (lo = a, hi = b).
__device__ __forceinline__ uint32_t pack_f16x2(float a, float b) {
    uint32_t r;
    asm("cvt.rn.f16x2.f32 %0, %1, %2;" : "=r"(r) : "f"(b), "f"(a));
    return r;
}

// fp16 MMA, fp32 accumulate.
__device__ __forceinline__ void mma_m16n8k16_f16(float c[4],
                                                 uint32_t a0, uint32_t a1, uint32_t a2, uint32_t a3,
                                                 uint32_t b0, uint32_t b1) {
    asm volatile(
        "mma.sync.aligned.m16n8k16.row.col.f32.f16.f16.f32 "
        "{%0,%1,%2,%3}, {%4,%5,%6,%7}, {%8,%9}, {%0,%1,%2,%3};\n"
        : "+f"(c[0]), "+f"(c[1]), "+f"(c[2]), "+f"(c[3])
        : "r"(a0), "r"(a1), "r"(a2), "r"(a3), "r"(b0), "r"(b1));
}

#define LDSM_X4(r0, r1, r2, r3, addr) \
    asm volatile("ldmatrix.sync.aligned.m8n8.x4.shared.b16 {%0,%1,%2,%3}, [%4];" \
                 : "=r"(r0), "=r"(r1), "=r"(r2), "=r"(r3) : "r"(addr))
#define LDSM_X4_TRANS(r0, r1, r2, r3, addr) \
    asm volatile("ldmatrix.sync.aligned.m8n8.x4.trans.shared.b16 {%0,%1,%2,%3}, [%4];" \
                 : "=r"(r0), "=r"(r1), "=r"(r2), "=r"(r3) : "r"(addr))
#define LDSM_X2_TRANS(r0, r1, addr) \
    asm volatile("ldmatrix.sync.aligned.m8n8.x2.trans.shared.b16 {%0,%1}, [%2];" \
                 : "=r"(r0), "=r"(r1) : "r"(addr))

#define CP_ASYNC16(dst_smem_u32, src_gmem_ptr) \
    asm volatile("cp.async.cg.shared.global [%0], [%1], 16;\n" \
                 :: "r"(dst_smem_u32), "l"(src_gmem_ptr))
#define CP_ASYNC8(dst_smem_u32, src_gmem_ptr) \
    asm volatile("cp.async.ca.shared.global [%0], [%1], 8;\n" \
                 :: "r"(dst_smem_u32), "l"(src_gmem_ptr))
#define CP_COMMIT() asm volatile("cp.async.commit_group;\n" ::: "memory")
#define CP_WAIT1()  asm volatile("cp.async.wait_group 1;\n" ::: "memory")
#define CP_WAIT0()  asm volatile("cp.async.wait_group 0;\n" ::: "memory")

// Q pre-scale: 1/sqrt(DK) * log2(e)  -> scores land in log2 domain; exp == ex2.
__device__ __forceinline__ float qscale() { return 1.4426950408889634f / 8.0f; }

// ---------------------------------------------------------------------------
// Batched fp32 -> fp16 conversion: one launch converts all 7 tensors.
__global__ __launch_bounds__(256) void cvt_f16_batch_kernel(
    const float4* __restrict__ s0, const float4* __restrict__ s1,
    const float4* __restrict__ s2, const float4* __restrict__ s3,
    const float4* __restrict__ s4, const float4* __restrict__ s5,
    const float4* __restrict__ s6,
    __half* __restrict__ d0, __half* __restrict__ d1, __half* __restrict__ d2,
    __half* __restrict__ d3, __half* __restrict__ d4, __half* __restrict__ d5,
    __half* __restrict__ d6,
    int na4, int nw4)
{
    const int t = blockIdx.y;
    const float4* src = (t == 0) ? s0 : (t == 1) ? s1 : (t == 2) ? s2
                       : (t == 3) ? s3 : (t == 4) ? s4 : (t == 5) ? s5 : s6;
    __half* dst = (t == 0) ? d0 : (t == 1) ? d1 : (t == 2) ? d2
                 : (t == 3) ? d3 : (t == 4) ? d4 : (t == 5) ? d5 : d6;
    const int n4 = (t < 3) ? na4 : nw4;

    int i = blockIdx.x * 256 + threadIdx.x;
    int stride = gridDim.x * 256;
    for (; i < n4; i += stride) {
        float4 v = src[i];
        uint2 o;
        o.x = pack_f16x2(v.x, v.y);
        o.y = pack_f16x2(v.z, v.w);
        *(uint2*)(dst + (size_t)i * 4) = o;
    }
}

__global__ __launch_bounds__(256) void pack_mask_kernel(
    const int* __restrict__ mask, uint32_t* __restrict__ out)
{
    int idx = blockIdx.x * 256 + threadIdx.x;
    int v = mask[idx] > 0 ? 1 : 0;
    uint32_t bal = __ballot_sync(0xffffffffu, v);
    if ((threadIdx.x & 31) == 0) out[idx >> 5] = bal;
}

// ---------------------------------------------------------------------------
// fp16 GEMM (proven R14): 128x128 CTA tile, 4 warps in 2x2, warp tile 64x64,
// K-tile 64, 2-stage cp.async, ldmatrix frag loads.
namespace {
constexpr int LDH    = 72;
constexpr int TILE_B = 128 * LDH * 2;
constexpr int STG_B  = 2 * TILE_B;
constexpr int GEMM_SMEM_BYTES = 2 * STG_B;  // 73728
}

__global__ __launch_bounds__(128, 2) void gemm3_nt_bias(
    const __half* __restrict__ A0, const __half* __restrict__ A1, const __half* __restrict__ A2,
    const __half* __restrict__ W0, const __half* __restrict__ W1, const __half* __restrict__ W2,
    const float* __restrict__ bb0, const float* __restrict__ bb1, const float* __restrict__ bb2,
    void* __restrict__ C0, void* __restrict__ C1, void* __restrict__ C2,
    int M, int N, int K, int out_mode)
{
    extern __shared__ char smc[];

    const int z = blockIdx.z;
    const __half* A   = (z == 0) ? A0 : (z == 1) ? A1 : A2;
    const __half* W   = (z == 0) ? W0 : (z == 1) ? W1 : W2;
    const float* bias = (z == 0) ? bb0 : (z == 1) ? bb1 : bb2;
    void*        Cv   = (z == 0) ? C0 : (z == 1) ? C1 : C2;
    const float scale = (out_mode == 1 && z == 0) ? qscale() : 1.0f;

    const int tid  = threadIdx.x;
    const int lane = tid & 31;
    const int warp = tid >> 5;
    const int g    = lane >> 2;
    const int tg   = lane & 3;
    const int wm   = warp >> 1;
    const int wn   = warp & 1;
    const int row0 = blockIdx.y * 128;
    const int col0 = blockIdx.x * 128;

    const int lr = lane & 7;
    const int lm = lane >> 3;
    const uint32_t smem_u32 = (uint32_t)__cvta_generic_to_shared(smc);

    uint32_t offA[4];
    #pragma unroll
    for (int mt = 0; mt < 4; mt++)
        offA[mt] = (uint32_t)(((wm * 64 + mt * 16 + (lm & 1) * 8 + lr) * LDH
                               + (lm >> 1) * 8) * 2);
    uint32_t offB[4];
    #pragma unroll
    for (int np = 0; np < 4; np++)
        offB[np] = (uint32_t)(TILE_B + ((wn * 64 + np * 16 + (lm >> 1) * 8 + lr) * LDH) * 2
                              + (lm & 1) * 16);

    auto issue_stage = [&](int s, int k0) {
        #pragma unroll
        for (int i = 0; i < 8; i++) {
            int lin = tid + i * 128;
            int r   = lin >> 3;
            int c16 = lin & 7;
            uint32_t da = smem_u32 + (uint32_t)(s * STG_B + r * LDH * 2 + c16 * 16);
            CP_ASYNC16(da, A + (size_t)(row0 + r) * K + k0 + c16 * 8);
            uint32_t db = smem_u32 + (uint32_t)(s * STG_B + TILE_B + r * LDH * 2 + c16 * 16);
            CP_ASYNC16(db, W + (size_t)(col0 + r) * K + k0 + c16 * 8);
        }
        CP_COMMIT();
    };

    float acc[4][8][4];
    #pragma unroll
    for (int mt = 0; mt < 4; mt++)
        #pragma unroll
        for (int nt = 0; nt < 8; nt++)
            #pragma unroll
            for (int i = 0; i < 4; i++) acc[mt][nt][i] = 0.f;

    const int nk = K / 64;
    issue_stage(0, 0);

    for (int kt = 0; kt < nk; kt++) {
        const int cur = kt & 1;
        if (kt + 1 < nk) { issue_stage(cur ^ 1, (kt + 1) * 64); CP_WAIT1(); }
        else             { CP_WAIT0(); }
        __syncthreads();

        const uint32_t sbase = smem_u32 + (uint32_t)(cur * STG_B);

        #pragma unroll
        for (int ks = 0; ks < 4; ks++) {
            uint32_t af[4][4];
            uint32_t bf[8][2];
            #pragma unroll
            for (int mt = 0; mt < 4; mt++)
                LDSM_X4(af[mt][0], af[mt][1], af[mt][2], af[mt][3],
                        sbase + offA[mt] + ks * 32);
            #pragma unroll
            for (int np = 0; np < 4; np++)
                LDSM_X4(bf[2 * np][0], bf[2 * np][1], bf[2 * np + 1][0], bf[2 * np + 1][1],
                        sbase + offB[np] + ks * 32);
            #pragma unroll
            for (int mt = 0; mt < 4; mt++)
                #pragma unroll
                for (int nt = 0; nt < 8; nt++)
                    mma_m16n8k16_f16(acc[mt][nt], af[mt][0], af[mt][1], af[mt][2], af[mt][3],
                                     bf[nt][0], bf[nt][1]);
        }
        __syncthreads();
    }

    #pragma unroll
    for (int mt = 0; mt < 4; mt++) {
        int r = row0 + wm * 64 + mt * 16 + g;
        #pragma unroll
        for (int nt = 0; nt < 8; nt++) {
            int c = col0 + wn * 64 + nt * 8 + 2 * tg;
            float b0v = bias[c], b1v = bias[c + 1];
            float o00 = acc[mt][nt][0] + b0v, o01 = acc[mt][nt][1] + b1v;
            float o10 = acc[mt][nt][2] + b0v, o11 = acc[mt][nt][3] + b1v;
            if (out_mode == 1) {
                __half* Ch = (__half*)Cv;
                *(uint32_t*)(Ch + (size_t)r * N + c)       = pack_f16x2(o00 * scale, o01 * scale);
                *(uint32_t*)(Ch + (size_t)(r + 8) * N + c) = pack_f16x2(o10 * scale, o11 * scale);
            } else {
                float* Cf = (float*)Cv;
                *(float2*)(Cf + (size_t)r * N + c)       = make_float2(o00, o01);
                *(float2*)(Cf + (size_t)(r + 8) * N + c) = make_float2(o10, o11);
            }
        }
    }
}

// ---------------------------------------------------------------------------
// fp16 flash attention v3: CTA q-tile 128 (two 16-row m-tiles per warp).
// Each K/V fragment load now feeds 2x the MMAs -> L1 wavefronts per FLOP
// halved (the R14 ceiling). log2-domain ex2 softmax, additive mask LUT,
// ones-column row sums, cp.async double buffer.
namespace {
constexpr int AH_LD  = 72;
constexpr int AK_ST  = 64 * AH_LD;
constexpr int A_KS_B = 0;
constexpr int A_VS_B = 2 * AK_ST * 2;            // 18432
constexpr int A_MB_B = A_VS_B + 2 * AK_ST * 2;   // 36864
constexpr int A_LUT_B = A_MB_B + 2 * 256 * 4;    // 38912 (128 rows x 2 words x 2 stages)
constexpr int ATTN_SMEM_BYTES = A_LUT_B + 16;    // 38928
}

__global__ __launch_bounds__(128, 2) void attn_kernel(
    const __half* __restrict__ Qh, const __half* __restrict__ Kh,
    const __half* __restrict__ Vh, const uint32_t* __restrict__ mbits,
    __half* __restrict__ Xh)
{
    extern __shared__ char smc[];
    uint32_t* MbB = (uint32_t*)(smc + A_MB_B);
    const uint32_t* lutS = (const uint32_t*)(smc + A_LUT_B);
    const uint32_t smem_u32 = (uint32_t)__cvta_generic_to_shared(smc);

    const int tid  = threadIdx.x;
    const int lane = tid & 31;
    const int warp = tid >> 5;
    const int g    = lane >> 2;
    const int tg   = lane & 3;
    const int lr   = lane & 7;
    const int lm   = lane >> 3;

    const int h  = blockIdx.x;
    const int q0 = blockIdx.y * 128;
    const int b  = blockIdx.z;

    // One-time smem init: V pad columns (col 64 = 1.0, 65-71 = 0) + mask LUT.
    {
        int st = tid >> 6;
        int r  = tid & 63;
        *(uint4*)(smc + A_VS_B + st * (AK_ST * 2) + r * (AH_LD * 2) + 128) =
            make_uint4(0x00003C00u, 0u, 0u, 0u);
        if (tid < 4) {
            const uint32_t lut_init[4] = {0u, 0x0000D380u, 0xD3800000u, 0xD380D380u};
            ((uint32_t*)(smc + A_LUT_B))[tid] = lut_init[tid];
        }
    }

    uint32_t offK[4];
    #pragma unroll
    for (int np = 0; np < 4; np++)
        offK[np] = (uint32_t)((np * 16 + (lm >> 1) * 8 + lr) * AH_LD * 2 + (lm & 1) * 16);
    uint32_t offV[4];
    #pragma unroll
    for (int np = 0; np < 4; np++)
        offV[np] = (uint32_t)(A_VS_B + ((lm & 1) * 8 + lr) * AH_LD * 2
                              + (np * 16 + (lm >> 1) * 8) * 2);
    const uint32_t offV1 = (uint32_t)(A_VS_B + (((lane >> 3) & 1) * 8 + lr) * AH_LD * 2 + 128);

    auto issue_stage = [&](int st, int k0) {
        #pragma unroll
        for (int i = 0; i < 4; i++) {
            int lin = tid + i * 128;
            int r   = lin >> 3;
            int c16 = lin & 7;
            const size_t gro = ((size_t)(b * S_ + k0 + r)) * D_ + h * DK_ + c16 * 8;
            uint32_t dk = smem_u32 + (uint32_t)(A_KS_B + st * AK_ST * 2 + r * AH_LD * 2 + c16 * 16);
            CP_ASYNC16(dk, Kh + gro);
            uint32_t dv = smem_u32 + (uint32_t)(A_VS_B + st * AK_ST * 2 + r * AH_LD * 2 + c16 * 16);
            CP_ASYNC16(dv, Vh + gro);
        }
        // mask rows q0..q0+127: every thread loads one row's 2 words (8B)
        uint32_t dm = smem_u32 + (uint32_t)(A_MB_B + (st * 256 + tid * 2) * 4);
        CP_ASYNC8(dm, mbits + ((size_t)(b * S_ + q0 + tid)) * 64 + (k0 >> 5));
        CP_COMMIT();
    };

    // Q fragments, two m-tiles (rows warp*16 and 64+warp*16), pre-scaled log2e/8.
    uint32_t qf[2][4][4];
    #pragma unroll
    for (int mt = 0; mt < 2; mt++) {
        const int qrow = q0 + mt * 64 + warp * 16 + g;
        const __half* qp0 = Qh + ((size_t)(b * S_ + qrow)) * D_ + h * DK_;
        const __half* qp1 = qp0 + (size_t)8 * D_;
        #pragma unroll
        for (int ks = 0; ks < 4; ks++) {
            qf[mt][ks][0] = *(const uint32_t*)(qp0 + ks * 16 + 2 * tg);
            qf[mt][ks][1] = *(const uint32_t*)(qp1 + ks * 16 + 2 * tg);
            qf[mt][ks][2] = *(const uint32_t*)(qp0 + ks * 16 + 2 * tg + 8);
            qf[mt][ks][3] = *(const uint32_t*)(qp1 + ks * 16 + 2 * tg + 8);
        }
    }

    float oacc[2][8][4];
    #pragma unroll
    for (int mt = 0; mt < 2; mt++)
        #pragma unroll
        for (int nt = 0; nt < 8; nt++)
            #pragma unroll
            for (int i = 0; i < 4; i++) oacc[mt][nt][i] = 0.f;
    float oacc9[2][4];
    #pragma unroll
    for (int mt = 0; mt < 2; mt++)
        #pragma unroll
        for (int i = 0; i < 4; i++) oacc9[mt][i] = 0.f;

    const int r0l = warp * 16 + g;

    constexpr int NJ = S_ / 64;
    issue_stage(0, 0);

    for (int j = 0; j < NJ; j++) {
        const int cur = j & 1;
        if (j + 1 < NJ) { issue_stage(cur ^ 1, (j + 1) * 64); CP_WAIT1(); }
        else            { CP_WAIT0(); }
        __syncthreads();

        const uint32_t kbase = smem_u32 + (uint32_t)(cur * AK_ST * 2);
        const uint32_t* Mcur = MbB + cur * 256;

        // S for both m-tiles; each bk load feeds 2 MMAs.
        float sacc0[8][4], sacc1[8][4];
        #pragma unroll
        for (int nt = 0; nt < 8; nt++) {
            sacc0[nt][0] = 0.f; sacc0[nt][1] = 0.f; sacc0[nt][2] = 0.f; sacc0[nt][3] = 0.f;
            sacc1[nt][0] = 0.f; sacc1[nt][1] = 0.f; sacc1[nt][2] = 0.f; sacc1[nt][3] = 0.f;
        }
        #pragma unroll
        for (int ks = 0; ks < 4; ks++) {
            uint32_t bk[8][2];
            #pragma unroll
            for (int np = 0; np < 4; np++)
                LDSM_X4(bk[2 * np][0], bk[2 * np][1], bk[2 * np + 1][0], bk[2 * np + 1][1],
                        kbase + offK[np] + ks * 32);
            #pragma unroll
            for (int nt = 0; nt < 8; nt++) {
                mma_m16n8k16_f16(sacc0[nt], qf[0][ks][0], qf[0][ks][1], qf[0][ks][2], qf[0][ks][3],
                                 bk[nt][0], bk[nt][1]);
                mma_m16n8k16_f16(sacc1[nt], qf[1][ks][0], qf[1][ks][1], qf[1][ks][2], qf[1][ks][3],
                                 bk[nt][0], bk[nt][1]);
            }
        }

        // softmax both m-tiles -> fp16 A-fragments
        uint32_t ph[2][8][2];
        #pragma unroll
        for (int mt = 0; mt < 2; mt++) {
            const int rr = mt * 64 + r0l;
            const uint32_t wA = Mcur[rr * 2],       wB = Mcur[rr * 2 + 1];
            const uint32_t wC = Mcur[(rr + 8) * 2], wD = Mcur[(rr + 8) * 2 + 1];
            float (*sa)[4] = (mt == 0) ? sacc0 : sacc1;
            #pragma unroll
            for (int nt = 0; nt < 8; nt++) {
                int sh = (nt * 8 + 2 * tg) & 31;
                uint32_t wa = (nt < 4) ? wA : wB;
                uint32_t wb = (nt < 4) ? wC : wD;
                uint32_t bias0 = lutS[(wa >> sh) & 3u];
                uint32_t bias1 = lutS[(wb >> sh) & 3u];
                uint32_t h0 = pack_f16x2(sa[nt][0], sa[nt][1]);
                uint32_t h1 = pack_f16x2(sa[nt][2], sa[nt][3]);
                uint32_t e0, e1;
                asm("add.rn.f16x2 %0, %1, %2;" : "=r"(e0) : "r"(h0), "r"(bias0));
                asm("add.rn.f16x2 %0, %1, %2;" : "=r"(e1) : "r"(h1), "r"(bias1));
                asm("ex2.approx.f16x2 %0, %1;" : "=r"(ph[mt][nt][0]) : "r"(e0));
                asm("ex2.approx.f16x2 %0, %1;" : "=r"(ph[mt][nt][1]) : "r"(e1));
            }
        }

        // O += P @ V for both m-tiles; each bv load feeds 2 MMAs.
        #pragma unroll
        for (int j2 = 0; j2 < 4; j2++) {
            uint32_t bv[8][2];
            #pragma unroll
            for (int np = 0; np < 4; np++)
                LDSM_X4_TRANS(bv[2 * np][0], bv[2 * np][1], bv[2 * np + 1][0], bv[2 * np + 1][1],
                              kbase + offV[np] + j2 * (16 * AH_LD * 2));
            uint32_t bo0, bo1;
            LDSM_X2_TRANS(bo0, bo1, kbase + offV1 + j2 * (16 * AH_LD * 2));
            #pragma unroll
            for (int nt = 0; nt < 8; nt++) {
                mma_m16n8k16_f16(oacc[0][nt],
                                 ph[0][2 * j2][0], ph[0][2 * j2][1],
                                 ph[0][2 * j2 + 1][0], ph[0][2 * j2 + 1][1],
                                 bv[nt][0], bv[nt][1]);
                mma_m16n8k16_f16(oacc[1][nt],
                                 ph[1][2 * j2][0], ph[1][2 * j2][1],
                                 ph[1][2 * j2 + 1][0], ph[1][2 * j2 + 1][1],
                                 bv[nt][0], bv[nt][1]);
            }
            mma_m16n8k16_f16(oacc9[0],
                             ph[0][2 * j2][0], ph[0][2 * j2][1],
                             ph[0][2 * j2 + 1][0], ph[0][2 * j2 + 1][1], bo0, bo1);
            mma_m16n8k16_f16(oacc9[1],
                             ph[1][2 * j2][0], ph[1][2 * j2][1],
                             ph[1][2 * j2 + 1][0], ph[1][2 * j2 + 1][1], bo0, bo1);
        }
        __syncthreads();
    }

    // Row sums in col 64 -> lane (4g); normalize and store both m-tiles.
    #pragma unroll
    for (int mt = 0; mt < 2; mt++) {
        float l0 = __shfl_sync(0xffffffffu, oacc9[mt][0], lane & 28);
        float l1 = __shfl_sync(0xffffffffu, oacc9[mt][2], lane & 28);
        float inv0 = 1.f / l0;
        float inv1 = 1.f / l1;
        int r = q0 + mt * 64 + r0l;
        #pragma unroll
        for (int nt = 0; nt < 8; nt++) {
            int c = h * DK_ + nt * 8 + 2 * tg;
            *(uint32_t*)(Xh + ((size_t)(b * S_ + r)) * D_ + c) =
                pack_f16x2(oacc[mt][nt][0] * inv0, oacc[mt][nt][1] * inv0);
            *(uint32_t*)(Xh + ((size_t)(b * S_ + r + 8)) * D_ + c) =
                pack_f16x2(oacc[mt][nt][2] * inv1, oacc[mt][nt][3] * inv1);
        }
    }
}

extern "C" void kernel_launch(void* const* d_in, const int* in_sizes, int n_in,
                              void* d_out, int out_size) {
    (void)in_sizes; (void)n_in; (void)out_size;
    const float* query = (const float*)d_in[0];
    const float* key   = (const float*)d_in[1];
    const float* value = (const float*)d_in[2];
    const int*   mask  = (const int*)d_in[3];
    const float* Wq = (const float*)d_in[4];
    const float* bq = (const float*)d_in[5];
    const float* Wk = (const float*)d_in[6];
    const float* bk = (const float*)d_in[7];
    const float* Wv = (const float*)d_in[8];
    const float* bv = (const float*)d_in[9];
    const float* Wo = (const float*)d_in[10];
    const float* bo = (const float*)d_in[11];
    float* out = (float*)d_out;

    __half *pQh, *pKh, *pVh, *pXh;
    __half *pAq, *pAk, *pAv, *pWq, *pWk, *pWv, *pWo;
    uint32_t* pMb;
    cudaGetSymbolAddress((void**)&pQh, g_Qh);
    cudaGetSymbolAddress((void**)&pKh, g_Kh);
    cudaGetSymbolAddress((void**)&pVh, g_Vh);
    cudaGetSymbolAddress((void**)&pXh, g_Xh);
    cudaGetSymbolAddress((void**)&pAq, g_Ahq);
    cudaGetSymbolAddress((void**)&pAk, g_Ahk);
    cudaGetSymbolAddress((void**)&pAv, g_Ahv);
    cudaGetSymbolAddress((void**)&pWq, g_Whq);
    cudaGetSymbolAddress((void**)&pWk, g_Whk);
    cudaGetSymbolAddress((void**)&pWv, g_Whv);
    cudaGetSymbolAddress((void**)&pWo, g_Who);
    cudaGetSymbolAddress((void**)&pMb, g_Mb);

    static bool attr_done = false;
    if (!attr_done) {
        cudaFuncSetAttribute(gemm3_nt_bias,
                             cudaFuncAttributeMaxDynamicSharedMemorySize, GEMM_SMEM_BYTES);
        cudaFuncSetAttribute(attn_kernel,
                             cudaFuncAttributeMaxDynamicSharedMemorySize, ATTN_SMEM_BYTES);
        attr_done = true;
    }

    const int M = B_ * S_;
    const int NA4 = (B_ * S_ * D_) / 4;
    const int NW4 = (D_ * D_) / 4;

    // mask bit-pack + one batched fp16 conversion launch for all operands
    pack_mask_kernel<<<(B_ * S_ * S_) / 256, 256>>>(mask, pMb);
    cvt_f16_batch_kernel<<<dim3(1024, 7), 256>>>(
        (const float4*)query, (const float4*)key, (const float4*)value,
        (const float4*)Wq, (const float4*)Wk, (const float4*)Wv, (const float4*)Wo,
        pAq, pAk, pAv, pWq, pWk, pWv, pWo, NA4, NW4);

    // fused QKV projections -> fp16 outputs (Q scaled by log2e/8 in epilogue)
    dim3 gq(D_ / 128, M / 128, 3);
    gemm3_nt_bias<<<gq, 128, GEMM_SMEM_BYTES>>>(
        pAq, pAk, pAv, pWq, pWk, pWv, bq, bk, bv,
        (void*)pQh, (void*)pKh, (void*)pVh, M, D_, D_, 1);

    attn_kernel<<<dim3(H_, S_ / 128, B_), 128, ATTN_SMEM_BYTES>>>(pQh, pKh, pVh, pMb, pXh);

    // output projection (fp16 inputs), fp32 out
    dim3 go(D_ / 128, M / 128, 1);
    gemm3_nt_bias<<<go, 128, GEMM_SMEM_BYTES>>>(
        pXh, pXh, pXh, pWo, pWo, pWo, bo, bo, bo,
        (void*)out, (void*)out, (void*)out, M, D_, D_, 0);
}

// round 16
// speedup vs baseline: 1.0308x; 1.0308x over previous
#include <cuda_runtime.h>
#include <cuda_fp16.h>
#include <cstdint>

namespace {
constexpr int B_  = 2;
constexpr int S_  = 2048;
constexpr int D_  = 1024;
constexpr int H_  = 16;
constexpr int DK_ = 64;
}

// Scratch (allocation-free rule: __device__ globals)
__device__ __half g_Qh[B_ * S_ * D_];   // fp16 Q (pre-scaled by log2e/8)
__device__ __half g_Kh[B_ * S_ * D_];
__device__ __half g_Vh[B_ * S_ * D_];
__device__ __half g_Xh[B_ * S_ * D_];   // fp16 attention output
__device__ __half g_Ahq[B_ * S_ * D_];  // fp16 activations
__device__ __half g_Ahk[B_ * S_ * D_];
__device__ __half g_Ahv[B_ * S_ * D_];
__device__ __half g_Whq[D_ * D_];       // fp16 weights
__device__ __half g_Whk[D_ * D_];
__device__ __half g_Whv[D_ * D_];
__device__ __half g_Who[D_ * D_];
__device__ uint32_t g_Mb[(B_ * S_ * S_) / 32];   // bit-packed mask

// Pack two fp32 to one fp16x2 register in a single cvt (lo = a, hi = b).
__device__ __forceinline__ uint32_t pack_f16x2(float a, float b) {
    uint32_t r;
    asm("cvt.rn.f16x2.f32 %0, %1, %2;" : "=r"(r) : "f"(b), "f"(a));
    return r;
}

// fp16 MMA, fp32 accumulate.
__device__ __forceinline__ void mma_m16n8k16_f16(float c[4],
                                                 uint32_t a0, uint32_t a1, uint32_t a2, uint32_t a3,
                                                 uint32_t b0, uint32_t b1) {
    asm volatile(
        "mma.sync.aligned.m16n8k16.row.col.f32.f16.f16.f32 "
        "{%0,%1,%2,%3}, {%4,%5,%6,%7}, {%8,%9}, {%0,%1,%2,%3};\n"
        : "+f"(c[0]), "+f"(c[1]), "+f"(c[2]), "+f"(c[3])
        : "r"(a0), "r"(a1), "r"(a2), "r"(a3), "r"(b0), "r"(b1));
}

// fp16 MMA, fp16 accumulate (C/D = 2 half2 regs). Used for QK: S lands
// directly in the half2 layout the softmax + PV A-fragments consume.
__device__ __forceinline__ void mma_m16n8k16_f16acc(uint32_t c[2],
                                                    uint32_t a0, uint32_t a1, uint32_t a2, uint32_t a3,
                                                    uint32_t b0, uint32_t b1) {
    asm volatile(
        "mma.sync.aligned.m16n8k16.row.col.f16.f16.f16.f16 "
        "{%0,%1}, {%2,%3,%4,%5}, {%6,%7}, {%0,%1};\n"
        : "+r"(c[0]), "+r"(c[1])
        : "r"(a0), "r"(a1), "r"(a2), "r"(a3), "r"(b0), "r"(b1));
}

#define LDSM_X4(r0, r1, r2, r3, addr) \
    asm volatile("ldmatrix.sync.aligned.m8n8.x4.shared.b16 {%0,%1,%2,%3}, [%4];" \
                 : "=r"(r0), "=r"(r1), "=r"(r2), "=r"(r3) : "r"(addr))
#define LDSM_X4_TRANS(r0, r1, r2, r3, addr) \
    asm volatile("ldmatrix.sync.aligned.m8n8.x4.trans.shared.b16 {%0,%1,%2,%3}, [%4];" \
                 : "=r"(r0), "=r"(r1), "=r"(r2), "=r"(r3) : "r"(addr))
#define LDSM_X2_TRANS(r0, r1, addr) \
    asm volatile("ldmatrix.sync.aligned.m8n8.x2.trans.shared.b16 {%0,%1}, [%2];" \
                 : "=r"(r0), "=r"(r1) : "r"(addr))

#define CP_ASYNC16(dst_smem_u32, src_gmem_ptr) \
    asm volatile("cp.async.cg.shared.global [%0], [%1], 16;\n" \
                 :: "r"(dst_smem_u32), "l"(src_gmem_ptr))
#define CP_ASYNC8(dst_smem_u32, src_gmem_ptr) \
    asm volatile("cp.async.ca.shared.global [%0], [%1], 8;\n" \
                 :: "r"(dst_smem_u32), "l"(src_gmem_ptr))
#define CP_COMMIT() asm volatile("cp.async.commit_group;\n" ::: "memory")
#define CP_WAIT1()  asm volatile("cp.async.wait_group 1;\n" ::: "memory")
#define CP_WAIT0()  asm volatile("cp.async.wait_group 0;\n" ::: "memory")

// Q pre-scale: 1/sqrt(DK) * log2(e)  -> scores land in log2 domain; exp == ex2.
__device__ __forceinline__ float qscale() { return 1.4426950408889634f / 8.0f; }

// ---------------------------------------------------------------------------
// Batched fp32 -> fp16 conversion: one launch converts all 7 tensors.
__global__ __launch_bounds__(256) void cvt_f16_batch_kernel(
    const float4* __restrict__ s0, const float4* __restrict__ s1,
    const float4* __restrict__ s2, const float4* __restrict__ s3,
    const float4* __restrict__ s4, const float4* __restrict__ s5,
    const float4* __restrict__ s6,
    __half* __restrict__ d0, __half* __restrict__ d1, __half* __restrict__ d2,
    __half* __restrict__ d3, __half* __restrict__ d4, __half* __restrict__ d5,
    __half* __restrict__ d6,
    int na4, int nw4)
{
    const int t = blockIdx.y;
    const float4* src = (t == 0) ? s0 : (t == 1) ? s1 : (t == 2) ? s2
                       : (t == 3) ? s3 : (t == 4) ? s4 : (t == 5) ? s5 : s6;
    __half* dst = (t == 0) ? d0 : (t == 1) ? d1 : (t == 2) ? d2
                 : (t == 3) ? d3 : (t == 4) ? d4 : (t == 5) ? d5 : d6;
    const int n4 = (t < 3) ? na4 : nw4;

    int i = blockIdx.x * 256 + threadIdx.x;
    int stride = gridDim.x * 256;
    for (; i < n4; i += stride) {
        float4 v = src[i];
        uint2 o;
        o.x = pack_f16x2(v.x, v.y);
        o.y = pack_f16x2(v.z, v.w);
        *(uint2*)(dst + (size_t)i * 4) = o;
    }
}

__global__ __launch_bounds__(256) void pack_mask_kernel(
    const int* __restrict__ mask, uint32_t* __restrict__ out)
{
    int idx = blockIdx.x * 256 + threadIdx.x;
    int v = mask[idx] > 0 ? 1 : 0;
    uint32_t bal = __ballot_sync(0xffffffffu, v);
    if ((threadIdx.x & 31) == 0) out[idx >> 5] = bal;
}

// ---------------------------------------------------------------------------
// fp16 GEMM (proven R14): 128x128 CTA tile, 4 warps in 2x2, warp tile 64x64,
// K-tile 64, 2-stage cp.async, ldmatrix frag loads.
namespace {
constexpr int LDH    = 72;
constexpr int TILE_B = 128 * LDH * 2;
constexpr int STG_B  = 2 * TILE_B;
constexpr int GEMM_SMEM_BYTES = 2 * STG_B;  // 73728
}

__global__ __launch_bounds__(128, 2) void gemm3_nt_bias(
    const __half* __restrict__ A0, const __half* __restrict__ A1, const __half* __restrict__ A2,
    const __half* __restrict__ W0, const __half* __restrict__ W1, const __half* __restrict__ W2,
    const float* __restrict__ bb0, const float* __restrict__ bb1, const float* __restrict__ bb2,
    void* __restrict__ C0, void* __restrict__ C1, void* __restrict__ C2,
    int M, int N, int K, int out_mode)
{
    extern __shared__ char smc[];

    const int z = blockIdx.z;
    const __half* A   = (z == 0) ? A0 : (z == 1) ? A1 : A2;
    const __half* W   = (z == 0) ? W0 : (z == 1) ? W1 : W2;
    const float* bias = (z == 0) ? bb0 : (z == 1) ? bb1 : bb2;
    void*        Cv   = (z == 0) ? C0 : (z == 1) ? C1 : C2;
    const float scale = (out_mode == 1 && z == 0) ? qscale() : 1.0f;

    const int tid  = threadIdx.x;
    const int lane = tid & 31;
    const int warp = tid >> 5;
    const int g    = lane >> 2;
    const int tg   = lane & 3;
    const int wm   = warp >> 1;
    const int wn   = warp & 1;
    const int row0 = blockIdx.y * 128;
    const int col0 = blockIdx.x * 128;

    const int lr = lane & 7;
    const int lm = lane >> 3;
    const uint32_t smem_u32 = (uint32_t)__cvta_generic_to_shared(smc);

    uint32_t offA[4];
    #pragma unroll
    for (int mt = 0; mt < 4; mt++)
        offA[mt] = (uint32_t)(((wm * 64 + mt * 16 + (lm & 1) * 8 + lr) * LDH
                               + (lm >> 1) * 8) * 2);
    uint32_t offB[4];
    #pragma unroll
    for (int np = 0; np < 4; np++)
        offB[np] = (uint32_t)(TILE_B + ((wn * 64 + np * 16 + (lm >> 1) * 8 + lr) * LDH) * 2
                              + (lm & 1) * 16);

    auto issue_stage = [&](int s, int k0) {
        #pragma unroll
        for (int i = 0; i < 8; i++) {
            int lin = tid + i * 128;
            int r   = lin >> 3;
            int c16 = lin & 7;
            uint32_t da = smem_u32 + (uint32_t)(s * STG_B + r * LDH * 2 + c16 * 16);
            CP_ASYNC16(da, A + (size_t)(row0 + r) * K + k0 + c16 * 8);
            uint32_t db = smem_u32 + (uint32_t)(s * STG_B + TILE_B + r * LDH * 2 + c16 * 16);
            CP_ASYNC16(db, W + (size_t)(col0 + r) * K + k0 + c16 * 8);
        }
        CP_COMMIT();
    };

    float acc[4][8][4];
    #pragma unroll
    for (int mt = 0; mt < 4; mt++)
        #pragma unroll
        for (int nt = 0; nt < 8; nt++)
            #pragma unroll
            for (int i = 0; i < 4; i++) acc[mt][nt][i] = 0.f;

    const int nk = K / 64;
    issue_stage(0, 0);

    for (int kt = 0; kt < nk; kt++) {
        const int cur = kt & 1;
        if (kt + 1 < nk) { issue_stage(cur ^ 1, (kt + 1) * 64); CP_WAIT1(); }
        else             { CP_WAIT0(); }
        __syncthreads();

        const uint32_t sbase = smem_u32 + (uint32_t)(cur * STG_B);

        #pragma unroll
        for (int ks = 0; ks < 4; ks++) {
            uint32_t af[4][4];
            uint32_t bf[8][2];
            #pragma unroll
            for (int mt = 0; mt < 4; mt++)
                LDSM_X4(af[mt][0], af[mt][1], af[mt][2], af[mt][3],
                        sbase + offA[mt] + ks * 32);
            #pragma unroll
            for (int np = 0; np < 4; np++)
                LDSM_X4(bf[2 * np][0], bf[2 * np][1], bf[2 * np + 1][0], bf[2 * np + 1][1],
                        sbase + offB[np] + ks * 32);
            #pragma unroll
            for (int mt = 0; mt < 4; mt++)
                #pragma unroll
                for (int nt = 0; nt < 8; nt++)
                    mma_m16n8k16_f16(acc[mt][nt], af[mt][0], af[mt][1], af[mt][2], af[mt][3],
                                     bf[nt][0], bf[nt][1]);
        }
        __syncthreads();
    }

    #pragma unroll
    for (int mt = 0; mt < 4; mt++) {
        int r = row0 + wm * 64 + mt * 16 + g;
        #pragma unroll
        for (int nt = 0; nt < 8; nt++) {
            int c = col0 + wn * 64 + nt * 8 + 2 * tg;
            float b0v = bias[c], b1v = bias[c + 1];
            float o00 = acc[mt][nt][0] + b0v, o01 = acc[mt][nt][1] + b1v;
            float o10 = acc[mt][nt][2] + b0v, o11 = acc[mt][nt][3] + b1v;
            if (out_mode == 1) {
                __half* Ch = (__half*)Cv;
                *(uint32_t*)(Ch + (size_t)r * N + c)       = pack_f16x2(o00 * scale, o01 * scale);
                *(uint32_t*)(Ch + (size_t)(r + 8) * N + c) = pack_f16x2(o10 * scale, o11 * scale);
            } else {
                float* Cf = (float*)Cv;
                *(float2*)(Cf + (size_t)r * N + c)       = make_float2(o00, o01);
                *(float2*)(Cf + (size_t)(r + 8) * N + c) = make_float2(o10, o11);
            }
        }
    }
}

// ---------------------------------------------------------------------------
// fp16 flash attention v4: CTA q-tile 128 (two m-tiles per warp) with QK in
// fp16-accumulator MMAs -> S lands directly in the half2 ph registers
// (no fp32 sacc, no packs; ~64 fewer live regs than v3 -> no spills).
// log2-domain ex2 softmax, additive mask LUT, ones-column row sums.
namespace {
constexpr int AH_LD  = 72;
constexpr int AK_ST  = 64 * AH_LD;
constexpr int A_KS_B = 0;
constexpr int A_VS_B = 2 * AK_ST * 2;            // 18432
constexpr int A_MB_B = A_VS_B + 2 * AK_ST * 2;   // 36864
constexpr int A_LUT_B = A_MB_B + 2 * 256 * 4;    // 38912
constexpr int ATTN_SMEM_BYTES = A_LUT_B + 16;    // 38928
}

__global__ __launch_bounds__(128, 2) void attn_kernel(
    const __half* __restrict__ Qh, const __half* __restrict__ Kh,
    const __half* __restrict__ Vh, const uint32_t* __restrict__ mbits,
    __half* __restrict__ Xh)
{
    extern __shared__ char smc[];
    uint32_t* MbB = (uint32_t*)(smc + A_MB_B);
    const uint32_t* lutS = (const uint32_t*)(smc + A_LUT_B);
    const uint32_t smem_u32 = (uint32_t)__cvta_generic_to_shared(smc);

    const int tid  = threadIdx.x;
    const int lane = tid & 31;
    const int warp = tid >> 5;
    const int g    = lane >> 2;
    const int tg   = lane & 3;
    const int lr   = lane & 7;
    const int lm   = lane >> 3;

    const int h  = blockIdx.x;
    const int q0 = blockIdx.y * 128;
    const int b  = blockIdx.z;

    // One-time smem init: V pad columns (col 64 = 1.0, 65-71 = 0) + mask LUT.
    {
        int st = tid >> 6;
        int r  = tid & 63;
        *(uint4*)(smc + A_VS_B + st * (AK_ST * 2) + r * (AH_LD * 2) + 128) =
            make_uint4(0x00003C00u, 0u, 0u, 0u);
        if (tid < 4) {
            const uint32_t lut_init[4] = {0u, 0x0000D380u, 0xD3800000u, 0xD380D380u};
            ((uint32_t*)(smc + A_LUT_B))[tid] = lut_init[tid];
        }
    }

    uint32_t offK[4];
    #pragma unroll
    for (int np = 0; np < 4; np++)
        offK[np] = (uint32_t)((np * 16 + (lm >> 1) * 8 + lr) * AH_LD * 2 + (lm & 1) * 16);
    uint32_t offV[4];
    #pragma unroll
    for (int np = 0; np < 4; np++)
        offV[np] = (uint32_t)(A_VS_B + ((lm & 1) * 8 + lr) * AH_LD * 2
                              + (np * 16 + (lm >> 1) * 8) * 2);
    const uint32_t offV1 = (uint32_t)(A_VS_B + (((lane >> 3) & 1) * 8 + lr) * AH_LD * 2 + 128);

    auto issue_stage = [&](int st, int k0) {
        #pragma unroll
        for (int i = 0; i < 4; i++) {
            int lin = tid + i * 128;
            int r   = lin >> 3;
            int c16 = lin & 7;
            const size_t gro = ((size_t)(b * S_ + k0 + r)) * D_ + h * DK_ + c16 * 8;
            uint32_t dk = smem_u32 + (uint32_t)(A_KS_B + st * AK_ST * 2 + r * AH_LD * 2 + c16 * 16);
            CP_ASYNC16(dk, Kh + gro);
            uint32_t dv = smem_u32 + (uint32_t)(A_VS_B + st * AK_ST * 2 + r * AH_LD * 2 + c16 * 16);
            CP_ASYNC16(dv, Vh + gro);
        }
        uint32_t dm = smem_u32 + (uint32_t)(A_MB_B + (st * 256 + tid * 2) * 4);
        CP_ASYNC8(dm, mbits + ((size_t)(b * S_ + q0 + tid)) * 64 + (k0 >> 5));
        CP_COMMIT();
    };

    // Q fragments, two m-tiles (rows warp*16 and 64+warp*16), pre-scaled log2e/8.
    uint32_t qf[2][4][4];
    #pragma unroll
    for (int mt = 0; mt < 2; mt++) {
        const int qrow = q0 + mt * 64 + warp * 16 + g;
        const __half* qp0 = Qh + ((size_t)(b * S_ + qrow)) * D_ + h * DK_;
        const __half* qp1 = qp0 + (size_t)8 * D_;
        #pragma unroll
        for (int ks = 0; ks < 4; ks++) {
            qf[mt][ks][0] = *(const uint32_t*)(qp0 + ks * 16 + 2 * tg);
            qf[mt][ks][1] = *(const uint32_t*)(qp1 + ks * 16 + 2 * tg);
            qf[mt][ks][2] = *(const uint32_t*)(qp0 + ks * 16 + 2 * tg + 8);
            qf[mt][ks][3] = *(const uint32_t*)(qp1 + ks * 16 + 2 * tg + 8);
        }
    }

    float oacc[2][8][4];
    #pragma unroll
    for (int mt = 0; mt < 2; mt++)
        #pragma unroll
        for (int nt = 0; nt < 8; nt++)
            #pragma unroll
            for (int i = 0; i < 4; i++) oacc[mt][nt][i] = 0.f;
    float oacc9[2][4];
    #pragma unroll
    for (int mt = 0; mt < 2; mt++)
        #pragma unroll
        for (int i = 0; i < 4; i++) oacc9[mt][i] = 0.f;

    const int r0l = warp * 16 + g;

    constexpr int NJ = S_ / 64;
    issue_stage(0, 0);

    for (int j = 0; j < NJ; j++) {
        const int cur = j & 1;
        if (j + 1 < NJ) { issue_stage(cur ^ 1, (j + 1) * 64); CP_WAIT1(); }
        else            { CP_WAIT0(); }
        __syncthreads();

        const uint32_t kbase = smem_u32 + (uint32_t)(cur * AK_ST * 2);
        const uint32_t* Mcur = MbB + cur * 256;

        // S (log2 domain, fp16 accumulator) -> directly in ph half2 layout.
        uint32_t ph[2][8][2];
        #pragma unroll
        for (int mt = 0; mt < 2; mt++)
            #pragma unroll
            for (int nt = 0; nt < 8; nt++) { ph[mt][nt][0] = 0u; ph[mt][nt][1] = 0u; }
        #pragma unroll
        for (int ks = 0; ks < 4; ks++) {
            uint32_t bk[8][2];
            #pragma unroll
            for (int np = 0; np < 4; np++)
                LDSM_X4(bk[2 * np][0], bk[2 * np][1], bk[2 * np + 1][0], bk[2 * np + 1][1],
                        kbase + offK[np] + ks * 32);
            #pragma unroll
            for (int nt = 0; nt < 8; nt++) {
                mma_m16n8k16_f16acc(ph[0][nt], qf[0][ks][0], qf[0][ks][1], qf[0][ks][2], qf[0][ks][3],
                                    bk[nt][0], bk[nt][1]);
                mma_m16n8k16_f16acc(ph[1][nt], qf[1][ks][0], qf[1][ks][1], qf[1][ks][2], qf[1][ks][3],
                                    bk[nt][0], bk[nt][1]);
            }
        }

        // softmax in place: p = ex2(s + mask_bias), two elements/instruction.
        #pragma unroll
        for (int mt = 0; mt < 2; mt++) {
            const int rr = mt * 64 + r0l;
            const uint32_t wA = Mcur[rr * 2],       wB = Mcur[rr * 2 + 1];
            const uint32_t wC = Mcur[(rr + 8) * 2], wD = Mcur[(rr + 8) * 2 + 1];
            #pragma unroll
            for (int nt = 0; nt < 8; nt++) {
                int sh = (nt * 8 + 2 * tg) & 31;
                uint32_t wa = (nt < 4) ? wA : wB;
                uint32_t wb = (nt < 4) ? wC : wD;
                uint32_t bias0 = lutS[(wa >> sh) & 3u];
                uint32_t bias1 = lutS[(wb >> sh) & 3u];
                uint32_t e0, e1;
                asm("add.rn.f16x2 %0, %1, %2;" : "=r"(e0) : "r"(ph[mt][nt][0]), "r"(bias0));
                asm("add.rn.f16x2 %0, %1, %2;" : "=r"(e1) : "r"(ph[mt][nt][1]), "r"(bias1));
                asm("ex2.approx.f16x2 %0, %1;" : "=r"(ph[mt][nt][0]) : "r"(e0));
                asm("ex2.approx.f16x2 %0, %1;" : "=r"(ph[mt][nt][1]) : "r"(e1));
            }
        }

        // O += P @ V for both m-tiles; each bv load feeds 2 MMAs.
        #pragma unroll
        for (int j2 = 0; j2 < 4; j2++) {
            uint32_t bv[8][2];
            #pragma unroll
            for (int np = 0; np < 4; np++)
                LDSM_X4_TRANS(bv[2 * np][0], bv[2 * np][1], bv[2 * np + 1][0], bv[2 * np + 1][1],
                              kbase + offV[np] + j2 * (16 * AH_LD * 2));
            uint32_t bo0, bo1;
            LDSM_X2_TRANS(bo0, bo1, kbase + offV1 + j2 * (16 * AH_LD * 2));
            #pragma unroll
            for (int nt = 0; nt < 8; nt++) {
                mma_m16n8k16_f16(oacc[0][nt],
                                 ph[0][2 * j2][0], ph[0][2 * j2][1],
                                 ph[0][2 * j2 + 1][0], ph[0][2 * j2 + 1][1],
                                 bv[nt][0], bv[nt][1]);
                mma_m16n8k16_f16(oacc[1][nt],
                                 ph[1][2 * j2][0], ph[1][2 * j2][1],
                                 ph[1][2 * j2 + 1][0], ph[1][2 * j2 + 1][1],
                                 bv[nt][0], bv[nt][1]);
            }
            mma_m16n8k16_f16(oacc9[0],
                             ph[0][2 * j2][0], ph[0][2 * j2][1],
                             ph[0][2 * j2 + 1][0], ph[0][2 * j2 + 1][1], bo0, bo1);
            mma_m16n8k16_f16(oacc9[1],
                             ph[1][2 * j2][0], ph[1][2 * j2][1],
                             ph[1][2 * j2 + 1][0], ph[1][2 * j2 + 1][1], bo0, bo1);
        }
        __syncthreads();
    }

    // Row sums in col 64 -> lane (4g); normalize and store both m-tiles.
    #pragma unroll
    for (int mt = 0; mt < 2; mt++) {
        float l0 = __shfl_sync(0xffffffffu, oacc9[mt][0], lane & 28);
        float l1 = __shfl_sync(0xffffffffu, oacc9[mt][2], lane & 28);
        float inv0 = 1.f / l0;
        float inv1 = 1.f / l1;
        int r = q0 + mt * 64 + r0l;
        #pragma unroll
        for (int nt = 0; nt < 8; nt++) {
            int c = h * DK_ + nt * 8 + 2 * tg;
            *(uint32_t*)(Xh + ((size_t)(b * S_ + r)) * D_ + c) =
                pack_f16x2(oacc[mt][nt][0] * inv0, oacc[mt][nt][1] * inv0);
            *(uint32_t*)(Xh + ((size_t)(b * S_ + r + 8)) * D_ + c) =
                pack_f16x2(oacc[mt][nt][2] * inv1, oacc[mt][nt][3] * inv1);
        }
    }
}

extern "C" void kernel_launch(void* const* d_in, const int* in_sizes, int n_in,
                              void* d_out, int out_size) {
    (void)in_sizes; (void)n_in; (void)out_size;
    const float* query = (const float*)d_in[0];
    const float* key   = (const float*)d_in[1];
    const float* value = (const float*)d_in[2];
    const int*   mask  = (const int*)d_in[3];
    const float* Wq = (const float*)d_in[4];
    const float* bq = (const float*)d_in[5];
    const float* Wk = (const float*)d_in[6];
    const float* bk = (const float*)d_in[7];
    const float* Wv = (const float*)d_in[8];
    const float* bv = (const float*)d_in[9];
    const float* Wo = (const float*)d_in[10];
    const float* bo = (const float*)d_in[11];
    float* out = (float*)d_out;

    __half *pQh, *pKh, *pVh, *pXh;
    __half *pAq, *pAk, *pAv, *pWq, *pWk, *pWv, *pWo;
    uint32_t* pMb;
    cudaGetSymbolAddress((void**)&pQh, g_Qh);
    cudaGetSymbolAddress((void**)&pKh, g_Kh);
    cudaGetSymbolAddress((void**)&pVh, g_Vh);
    cudaGetSymbolAddress((void**)&pXh, g_Xh);
    cudaGetSymbolAddress((void**)&pAq, g_Ahq);
    cudaGetSymbolAddress((void**)&pAk, g_Ahk);
    cudaGetSymbolAddress((void**)&pAv, g_Ahv);
    cudaGetSymbolAddress((void**)&pWq, g_Whq);
    cudaGetSymbolAddress((void**)&pWk, g_Whk);
    cudaGetSymbolAddress((void**)&pWv, g_Whv);
    cudaGetSymbolAddress((void**)&pWo, g_Who);
    cudaGetSymbolAddress((void**)&pMb, g_Mb);

    static bool attr_done = false;
    if (!attr_done) {
        cudaFuncSetAttribute(gemm3_nt_bias,
                             cudaFuncAttributeMaxDynamicSharedMemorySize, GEMM_SMEM_BYTES);
        cudaFuncSetAttribute(attn_kernel,
                             cudaFuncAttributeMaxDynamicSharedMemorySize, ATTN_SMEM_BYTES);
        attr_done = true;
    }

    const int M = B_ * S_;
    const int NA4 = (B_ * S_ * D_) / 4;
    const int NW4 = (D_ * D_) / 4;

    // mask bit-pack + one batched fp16 conversion launch for all operands
    pack_mask_kernel<<<(B_ * S_ * S_) / 256, 256>>>(mask, pMb);
    cvt_f16_batch_kernel<<<dim3(1024, 7), 256>>>(
        (const float4*)query, (const float4*)key, (const float4*)value,
        (const float4*)Wq, (const float4*)Wk, (const float4*)Wv, (const float4*)Wo,
        pAq, pAk, pAv, pWq, pWk, pWv, pWo, NA4, NW4);

    // fused QKV projections -> fp16 outputs (Q scaled by log2e/8 in epilogue)
    dim3 gq(D_ / 128, M / 128, 3);
    gemm3_nt_bias<<<gq, 128, GEMM_SMEM_BYTES>>>(
        pAq, pAk, pAv, pWq, pWk, pWv, bq, bk, bv,
        (void*)pQh, (void*)pKh, (void*)pVh, M, D_, D_, 1);

    attn_kernel<<<dim3(H_, S_ / 128, B_), 128, ATTN_SMEM_BYTES>>>(pQh, pKh, pVh, pMb, pXh);

    // output projection (fp16 inputs), fp32 out
    dim3 go(D_ / 128, M / 128, 1);
    gemm3_nt_bias<<<go, 128, GEMM_SMEM_BYTES>>>(
        pXh, pXh, pXh, pWo, pWo, pWo, bo, bo, bo,
        (void*)out, (void*)out, (void*)out, M, D_, D_, 0);
}

// round 17
// speedup vs baseline: 1.0597x; 1.0280x over previous
#include <cuda_runtime.h>
#include <cuda_fp16.h>
#include <cstdint>

namespace {
constexpr int B_  = 2;
constexpr int S_  = 2048;
constexpr int D_  = 1024;
constexpr int H_  = 16;
constexpr int DK_ = 64;
}

// Scratch (allocation-free rule: __device__ globals)
__device__ __half g_Qh[B_ * S_ * D_];   // fp16 Q (pre-scaled by log2e/8)
__device__ __half g_Kh[B_ * S_ * D_];
__device__ __half g_Vh[B_ * S_ * D_];
__device__ __half g_Xh[B_ * S_ * D_];   // fp16 attention output
__device__ __half g_Ahq[B_ * S_ * D_];  // fp16 activations
__device__ __half g_Ahk[B_ * S_ * D_];
__device__ __half g_Ahv[B_ * S_ * D_];
__device__ __half g_Whq[D_ * D_];       // fp16 weights
__device__ __half g_Whk[D_ * D_];
__device__ __half g_Whv[D_ * D_];
__device__ __half g_Who[D_ * D_];
__device__ uint32_t g_Mb[(B_ * S_ * S_) / 32];   // bit-packed mask

// Pack two fp32 to one fp16x2 register in a single cvt (lo = a, hi = b).
__device__ __forceinline__ uint32_t pack_f16x2(float a, float b) {
    uint32_t r;
    asm("cvt.rn.f16x2.f32 %0, %1, %2;" : "=r"(r) : "f"(b), "f"(a));
    return r;
}

// fp16 MMA, fp32 accumulate.
__device__ __forceinline__ void mma_m16n8k16_f16(float c[4],
                                                 uint32_t a0, uint32_t a1, uint32_t a2, uint32_t a3,
                                                 uint32_t b0, uint32_t b1) {
    asm volatile(
        "mma.sync.aligned.m16n8k16.row.col.f32.f16.f16.f32 "
        "{%0,%1,%2,%3}, {%4,%5,%6,%7}, {%8,%9}, {%0,%1,%2,%3};\n"
        : "+f"(c[0]), "+f"(c[1]), "+f"(c[2]), "+f"(c[3])
        : "r"(a0), "r"(a1), "r"(a2), "r"(a3), "r"(b0), "r"(b1));
}

// fp16 MMA, fp16 accumulate (C/D = 2 half2 regs). Used for QK: S lands
// directly in the half2 layout the softmax + PV A-fragments consume.
__device__ __forceinline__ void mma_m16n8k16_f16acc(uint32_t c[2],
                                                    uint32_t a0, uint32_t a1, uint32_t a2, uint32_t a3,
                                                    uint32_t b0, uint32_t b1) {
    asm volatile(
        "mma.sync.aligned.m16n8k16.row.col.f16.f16.f16.f16 "
        "{%0,%1}, {%2,%3,%4,%5}, {%6,%7}, {%0,%1};\n"
        : "+r"(c[0]), "+r"(c[1])
        : "r"(a0), "r"(a1), "r"(a2), "r"(a3), "r"(b0), "r"(b1));
}

#define LDSM_X4(r0, r1, r2, r3, addr) \
    asm volatile("ldmatrix.sync.aligned.m8n8.x4.shared.b16 {%0,%1,%2,%3}, [%4];" \
                 : "=r"(r0), "=r"(r1), "=r"(r2), "=r"(r3) : "r"(addr))
#define LDSM_X4_TRANS(r0, r1, r2, r3, addr) \
    asm volatile("ldmatrix.sync.aligned.m8n8.x4.trans.shared.b16 {%0,%1,%2,%3}, [%4];" \
                 : "=r"(r0), "=r"(r1), "=r"(r2), "=r"(r3) : "r"(addr))
#define LDSM_X2_TRANS(r0, r1, addr) \
    asm volatile("ldmatrix.sync.aligned.m8n8.x2.trans.shared.b16 {%0,%1}, [%2];" \
                 : "=r"(r0), "=r"(r1) : "r"(addr))

#define CP_ASYNC16(dst_smem_u32, src_gmem_ptr) \
    asm volatile("cp.async.cg.shared.global [%0], [%1], 16;\n" \
                 :: "r"(dst_smem_u32), "l"(src_gmem_ptr))
#define CP_ASYNC8(dst_smem_u32, src_gmem_ptr) \
    asm volatile("cp.async.ca.shared.global [%0], [%1], 8;\n" \
                 :: "r"(dst_smem_u32), "l"(src_gmem_ptr))
#define CP_COMMIT() asm volatile("cp.async.commit_group;\n" ::: "memory")
#define CP_WAIT1()  asm volatile("cp.async.wait_group 1;\n" ::: "memory")
#define CP_WAIT0()  asm volatile("cp.async.wait_group 0;\n" ::: "memory")

// Q pre-scale: 1/sqrt(DK) * log2(e)  -> scores land in log2 domain; exp == ex2.
__device__ __forceinline__ float qscale() { return 1.4426950408889634f / 8.0f; }

// ---------------------------------------------------------------------------
// Fused prologue: grid.y 0..6 convert the 7 fp32 tensors to fp16;
// grid.y == 7 bit-packs the mask. One launch -> conversions and mask
// packing overlap across SMs instead of running sequentially.
__global__ __launch_bounds__(256) void prologue_kernel(
    const float4* __restrict__ s0, const float4* __restrict__ s1,
    const float4* __restrict__ s2, const float4* __restrict__ s3,
    const float4* __restrict__ s4, const float4* __restrict__ s5,
    const float4* __restrict__ s6,
    __half* __restrict__ d0, __half* __restrict__ d1, __half* __restrict__ d2,
    __half* __restrict__ d3, __half* __restrict__ d4, __half* __restrict__ d5,
    __half* __restrict__ d6,
    const int* __restrict__ mask, uint32_t* __restrict__ mb,
    int na4, int nw4)
{
    const int t = blockIdx.y;
    if (t == 7) {
        int idx = blockIdx.x * 256 + threadIdx.x;
        int stride = gridDim.x * 256;
        const int n = B_ * S_ * S_;
        for (; idx < n; idx += stride) {
            int v = mask[idx] > 0 ? 1 : 0;
            uint32_t bal = __ballot_sync(0xffffffffu, v);
            if ((threadIdx.x & 31) == 0) mb[idx >> 5] = bal;
        }
        return;
    }
    const float4* src = (t == 0) ? s0 : (t == 1) ? s1 : (t == 2) ? s2
                       : (t == 3) ? s3 : (t == 4) ? s4 : (t == 5) ? s5 : s6;
    __half* dst = (t == 0) ? d0 : (t == 1) ? d1 : (t == 2) ? d2
                 : (t == 3) ? d3 : (t == 4) ? d4 : (t == 5) ? d5 : d6;
    const int n4 = (t < 3) ? na4 : nw4;

    int i = blockIdx.x * 256 + threadIdx.x;
    int stride = gridDim.x * 256;
    for (; i < n4; i += stride) {
        float4 v = src[i];
        uint2 o;
        o.x = pack_f16x2(v.x, v.y);
        o.y = pack_f16x2(v.z, v.w);
        *(uint2*)(dst + (size_t)i * 4) = o;
    }
}

// ---------------------------------------------------------------------------
// fp16 GEMM (proven R14): 128x128 CTA tile, 4 warps in 2x2, warp tile 64x64,
// K-tile 64, 2-stage cp.async, ldmatrix frag loads.
namespace {
constexpr int LDH    = 72;
constexpr int TILE_B = 128 * LDH * 2;
constexpr int STG_B  = 2 * TILE_B;
constexpr int GEMM_SMEM_BYTES = 2 * STG_B;  // 73728
}

__global__ __launch_bounds__(128, 2) void gemm3_nt_bias(
    const __half* __restrict__ A0, const __half* __restrict__ A1, const __half* __restrict__ A2,
    const __half* __restrict__ W0, const __half* __restrict__ W1, const __half* __restrict__ W2,
    const float* __restrict__ bb0, const float* __restrict__ bb1, const float* __restrict__ bb2,
    void* __restrict__ C0, void* __restrict__ C1, void* __restrict__ C2,
    int M, int N, int K, int out_mode)
{
    extern __shared__ char smc[];

    const int z = blockIdx.z;
    const __half* A   = (z == 0) ? A0 : (z == 1) ? A1 : A2;
    const __half* W   = (z == 0) ? W0 : (z == 1) ? W1 : W2;
    const float* bias = (z == 0) ? bb0 : (z == 1) ? bb1 : bb2;
    void*        Cv   = (z == 0) ? C0 : (z == 1) ? C1 : C2;
    const float scale = (out_mode == 1 && z == 0) ? qscale() : 1.0f;

    const int tid  = threadIdx.x;
    const int lane = tid & 31;
    const int warp = tid >> 5;
    const int g    = lane >> 2;
    const int tg   = lane & 3;
    const int wm   = warp >> 1;
    const int wn   = warp & 1;
    const int row0 = blockIdx.y * 128;
    const int col0 = blockIdx.x * 128;

    const int lr = lane & 7;
    const int lm = lane >> 3;
    const uint32_t smem_u32 = (uint32_t)__cvta_generic_to_shared(smc);

    uint32_t offA[4];
    #pragma unroll
    for (int mt = 0; mt < 4; mt++)
        offA[mt] = (uint32_t)(((wm * 64 + mt * 16 + (lm & 1) * 8 + lr) * LDH
                               + (lm >> 1) * 8) * 2);
    uint32_t offB[4];
    #pragma unroll
    for (int np = 0; np < 4; np++)
        offB[np] = (uint32_t)(TILE_B + ((wn * 64 + np * 16 + (lm >> 1) * 8 + lr) * LDH) * 2
                              + (lm & 1) * 16);

    auto issue_stage = [&](int s, int k0) {
        #pragma unroll
        for (int i = 0; i < 8; i++) {
            int lin = tid + i * 128;
            int r   = lin >> 3;
            int c16 = lin & 7;
            uint32_t da = smem_u32 + (uint32_t)(s * STG_B + r * LDH * 2 + c16 * 16);
            CP_ASYNC16(da, A + (size_t)(row0 + r) * K + k0 + c16 * 8);
            uint32_t db = smem_u32 + (uint32_t)(s * STG_B + TILE_B + r * LDH * 2 + c16 * 16);
            CP_ASYNC16(db, W + (size_t)(col0 + r) * K + k0 + c16 * 8);
        }
        CP_COMMIT();
    };

    float acc[4][8][4];
    #pragma unroll
    for (int mt = 0; mt < 4; mt++)
        #pragma unroll
        for (int nt = 0; nt < 8; nt++)
            #pragma unroll
            for (int i = 0; i < 4; i++) acc[mt][nt][i] = 0.f;

    const int nk = K / 64;
    issue_stage(0, 0);

    for (int kt = 0; kt < nk; kt++) {
        const int cur = kt & 1;
        if (kt + 1 < nk) { issue_stage(cur ^ 1, (kt + 1) * 64); CP_WAIT1(); }
        else             { CP_WAIT0(); }
        __syncthreads();

        const uint32_t sbase = smem_u32 + (uint32_t)(cur * STG_B);

        #pragma unroll
        for (int ks = 0; ks < 4; ks++) {
            uint32_t af[4][4];
            uint32_t bf[8][2];
            #pragma unroll
            for (int mt = 0; mt < 4; mt++)
                LDSM_X4(af[mt][0], af[mt][1], af[mt][2], af[mt][3],
                        sbase + offA[mt] + ks * 32);
            #pragma unroll
            for (int np = 0; np < 4; np++)
                LDSM_X4(bf[2 * np][0], bf[2 * np][1], bf[2 * np + 1][0], bf[2 * np + 1][1],
                        sbase + offB[np] + ks * 32);
            #pragma unroll
            for (int mt = 0; mt < 4; mt++)
                #pragma unroll
                for (int nt = 0; nt < 8; nt++)
                    mma_m16n8k16_f16(acc[mt][nt], af[mt][0], af[mt][1], af[mt][2], af[mt][3],
                                     bf[nt][0], bf[nt][1]);
        }
        __syncthreads();
    }

    #pragma unroll
    for (int mt = 0; mt < 4; mt++) {
        int r = row0 + wm * 64 + mt * 16 + g;
        #pragma unroll
        for (int nt = 0; nt < 8; nt++) {
            int c = col0 + wn * 64 + nt * 8 + 2 * tg;
            float b0v = bias[c], b1v = bias[c + 1];
            float o00 = acc[mt][nt][0] + b0v, o01 = acc[mt][nt][1] + b1v;
            float o10 = acc[mt][nt][2] + b0v, o11 = acc[mt][nt][3] + b1v;
            if (out_mode == 1) {
                __half* Ch = (__half*)Cv;
                *(uint32_t*)(Ch + (size_t)r * N + c)       = pack_f16x2(o00 * scale, o01 * scale);
                *(uint32_t*)(Ch + (size_t)(r + 8) * N + c) = pack_f16x2(o10 * scale, o11 * scale);
            } else {
                float* Cf = (float*)Cv;
                *(float2*)(Cf + (size_t)r * N + c)       = make_float2(o00, o01);
                *(float2*)(Cf + (size_t)(r + 8) * N + c) = make_float2(o10, o11);
            }
        }
    }
}

// ---------------------------------------------------------------------------
// fp16 flash attention (proven R16): CTA q-tile 128, QK in fp16-accumulator
// MMAs (S lands directly in ph half2 layout), log2-domain ex2 softmax,
// additive mask LUT, ones-column row sums, cp.async double buffer.
namespace {
constexpr int AH_LD  = 72;
constexpr int AK_ST  = 64 * AH_LD;
constexpr int A_KS_B = 0;
constexpr int A_VS_B = 2 * AK_ST * 2;            // 18432
constexpr int A_MB_B = A_VS_B + 2 * AK_ST * 2;   // 36864
constexpr int A_LUT_B = A_MB_B + 2 * 256 * 4;    // 38912
constexpr int ATTN_SMEM_BYTES = A_LUT_B + 16;    // 38928
}

__global__ __launch_bounds__(128, 2) void attn_kernel(
    const __half* __restrict__ Qh, const __half* __restrict__ Kh,
    const __half* __restrict__ Vh, const uint32_t* __restrict__ mbits,
    __half* __restrict__ Xh)
{
    extern __shared__ char smc[];
    uint32_t* MbB = (uint32_t*)(smc + A_MB_B);
    const uint32_t* lutS = (const uint32_t*)(smc + A_LUT_B);
    const uint32_t smem_u32 = (uint32_t)__cvta_generic_to_shared(smc);

    const int tid  = threadIdx.x;
    const int lane = tid & 31;
    const int warp = tid >> 5;
    const int g    = lane >> 2;
    const int tg   = lane & 3;
    const int lr   = lane & 7;
    const int lm   = lane >> 3;

    const int h  = blockIdx.x;
    const int q0 = blockIdx.y * 128;
    const int b  = blockIdx.z;

    // One-time smem init: V pad columns (col 64 = 1.0, 65-71 = 0) + mask LUT.
    {
        int st = tid >> 6;
        int r  = tid & 63;
        *(uint4*)(smc + A_VS_B + st * (AK_ST * 2) + r * (AH_LD * 2) + 128) =
            make_uint4(0x00003C00u, 0u, 0u, 0u);
        if (tid < 4) {
            const uint32_t lut_init[4] = {0u, 0x0000D380u, 0xD3800000u, 0xD380D380u};
            ((uint32_t*)(smc + A_LUT_B))[tid] = lut_init[tid];
        }
    }

    uint32_t offK[4];
    #pragma unroll
    for (int np = 0; np < 4; np++)
        offK[np] = (uint32_t)((np * 16 + (lm >> 1) * 8 + lr) * AH_LD * 2 + (lm & 1) * 16);
    uint32_t offV[4];
    #pragma unroll
    for (int np = 0; np < 4; np++)
        offV[np] = (uint32_t)(A_VS_B + ((lm & 1) * 8 + lr) * AH_LD * 2
                              + (np * 16 + (lm >> 1) * 8) * 2);
    const uint32_t offV1 = (uint32_t)(A_VS_B + (((lane >> 3) & 1) * 8 + lr) * AH_LD * 2 + 128);

    auto issue_stage = [&](int st, int k0) {
        #pragma unroll
        for (int i = 0; i < 4; i++) {
            int lin = tid + i * 128;
            int r   = lin >> 3;
            int c16 = lin & 7;
            const size_t gro = ((size_t)(b * S_ + k0 + r)) * D_ + h * DK_ + c16 * 8;
            uint32_t dk = smem_u32 + (uint32_t)(A_KS_B + st * AK_ST * 2 + r * AH_LD * 2 + c16 * 16);
            CP_ASYNC16(dk, Kh + gro);
            uint32_t dv = smem_u32 + (uint32_t)(A_VS_B + st * AK_ST * 2 + r * AH_LD * 2 + c16 * 16);
            CP_ASYNC16(dv, Vh + gro);
        }
        uint32_t dm = smem_u32 + (uint32_t)(A_MB_B + (st * 256 + tid * 2) * 4);
        CP_ASYNC8(dm, mbits + ((size_t)(b * S_ + q0 + tid)) * 64 + (k0 >> 5));
        CP_COMMIT();
    };

    // Q fragments, two m-tiles (rows warp*16 and 64+warp*16), pre-scaled log2e/8.
    uint32_t qf[2][4][4];
    #pragma unroll
    for (int mt = 0; mt < 2; mt++) {
        const int qrow = q0 + mt * 64 + warp * 16 + g;
        const __half* qp0 = Qh + ((size_t)(b * S_ + qrow)) * D_ + h * DK_;
        const __half* qp1 = qp0 + (size_t)8 * D_;
        #pragma unroll
        for (int ks = 0; ks < 4; ks++) {
            qf[mt][ks][0] = *(const uint32_t*)(qp0 + ks * 16 + 2 * tg);
            qf[mt][ks][1] = *(const uint32_t*)(qp1 + ks * 16 + 2 * tg);
            qf[mt][ks][2] = *(const uint32_t*)(qp0 + ks * 16 + 2 * tg + 8);
            qf[mt][ks][3] = *(const uint32_t*)(qp1 + ks * 16 + 2 * tg + 8);
        }
    }

    float oacc[2][8][4];
    #pragma unroll
    for (int mt = 0; mt < 2; mt++)
        #pragma unroll
        for (int nt = 0; nt < 8; nt++)
            #pragma unroll
            for (int i = 0; i < 4; i++) oacc[mt][nt][i] = 0.f;
    float oacc9[2][4];
    #pragma unroll
    for (int mt = 0; mt < 2; mt++)
        #pragma unroll
        for (int i = 0; i < 4; i++) oacc9[mt][i] = 0.f;

    const int r0l = warp * 16 + g;

    constexpr int NJ = S_ / 64;
    issue_stage(0, 0);

    for (int j = 0; j < NJ; j++) {
        const int cur = j & 1;
        if (j + 1 < NJ) { issue_stage(cur ^ 1, (j + 1) * 64); CP_WAIT1(); }
        else            { CP_WAIT0(); }
        __syncthreads();

        const uint32_t kbase = smem_u32 + (uint32_t)(cur * AK_ST * 2);
        const uint32_t* Mcur = MbB + cur * 256;

        // S (log2 domain, fp16 accumulator) -> directly in ph half2 layout.
        uint32_t ph[2][8][2];
        #pragma unroll
        for (int mt = 0; mt < 2; mt++)
            #pragma unroll
            for (int nt = 0; nt < 8; nt++) { ph[mt][nt][0] = 0u; ph[mt][nt][1] = 0u; }
        #pragma unroll
        for (int ks = 0; ks < 4; ks++) {
            uint32_t bk[8][2];
            #pragma unroll
            for (int np = 0; np < 4; np++)
                LDSM_X4(bk[2 * np][0], bk[2 * np][1], bk[2 * np + 1][0], bk[2 * np + 1][1],
                        kbase + offK[np] + ks * 32);
            #pragma unroll
            for (int nt = 0; nt < 8; nt++) {
                mma_m16n8k16_f16acc(ph[0][nt], qf[0][ks][0], qf[0][ks][1], qf[0][ks][2], qf[0][ks][3],
                                    bk[nt][0], bk[nt][1]);
                mma_m16n8k16_f16acc(ph[1][nt], qf[1][ks][0], qf[1][ks][1], qf[1][ks][2], qf[1][ks][3],
                                    bk[nt][0], bk[nt][1]);
            }
        }

        // softmax in place: p = ex2(s + mask_bias), two elements/instruction.
        #pragma unroll
        for (int mt = 0; mt < 2; mt++) {
            const int rr = mt * 64 + r0l;
            const uint32_t wA = Mcur[rr * 2],       wB = Mcur[rr * 2 + 1];
            const uint32_t wC = Mcur[(rr + 8) * 2], wD = Mcur[(rr + 8) * 2 + 1];
            #pragma unroll
            for (int nt = 0; nt < 8; nt++) {
                int sh = (nt * 8 + 2 * tg) & 31;
                uint32_t wa = (nt < 4) ? wA : wB;
                uint32_t wb = (nt < 4) ? wC : wD;
                uint32_t bias0 = lutS[(wa >> sh) & 3u];
                uint32_t bias1 = lutS[(wb >> sh) & 3u];
                uint32_t e0, e1;
                asm("add.rn.f16x2 %0, %1, %2;" : "=r"(e0) : "r"(ph[mt][nt][0]), "r"(bias0));
                asm("add.rn.f16x2 %0, %1, %2;" : "=r"(e1) : "r"(ph[mt][nt][1]), "r"(bias1));
                asm("ex2.approx.f16x2 %0, %1;" : "=r"(ph[mt][nt][0]) : "r"(e0));
                asm("ex2.approx.f16x2 %0, %1;" : "=r"(ph[mt][nt][1]) : "r"(e1));
            }
        }

        // O += P @ V for both m-tiles; each bv load feeds 2 MMAs.
        #pragma unroll
        for (int j2 = 0; j2 < 4; j2++) {
            uint32_t bv[8][2];
            #pragma unroll
            for (int np = 0; np < 4; np++)
                LDSM_X4_TRANS(bv[2 * np][0], bv[2 * np][1], bv[2 * np + 1][0], bv[2 * np + 1][1],
                              kbase + offV[np] + j2 * (16 * AH_LD * 2));
            uint32_t bo0, bo1;
            LDSM_X2_TRANS(bo0, bo1, kbase + offV1 + j2 * (16 * AH_LD * 2));
            #pragma unroll
            for (int nt = 0; nt < 8; nt++) {
                mma_m16n8k16_f16(oacc[0][nt],
                                 ph[0][2 * j2][0], ph[0][2 * j2][1],
                                 ph[0][2 * j2 + 1][0], ph[0][2 * j2 + 1][1],
                                 bv[nt][0], bv[nt][1]);
                mma_m16n8k16_f16(oacc[1][nt],
                                 ph[1][2 * j2][0], ph[1][2 * j2][1],
                                 ph[1][2 * j2 + 1][0], ph[1][2 * j2 + 1][1],
                                 bv[nt][0], bv[nt][1]);
            }
            mma_m16n8k16_f16(oacc9[0],
                             ph[0][2 * j2][0], ph[0][2 * j2][1],
                             ph[0][2 * j2 + 1][0], ph[0][2 * j2 + 1][1], bo0, bo1);
            mma_m16n8k16_f16(oacc9[1],
                             ph[1][2 * j2][0], ph[1][2 * j2][1],
                             ph[1][2 * j2 + 1][0], ph[1][2 * j2 + 1][1], bo0, bo1);
        }
        __syncthreads();
    }

    // Row sums in col 64 -> lane (4g); normalize and store both m-tiles.
    #pragma unroll
    for (int mt = 0; mt < 2; mt++) {
        float l0 = __shfl_sync(0xffffffffu, oacc9[mt][0], lane & 28);
        float l1 = __shfl_sync(0xffffffffu, oacc9[mt][2], lane & 28);
        float inv0 = 1.f / l0;
        float inv1 = 1.f / l1;
        int r = q0 + mt * 64 + r0l;
        #pragma unroll
        for (int nt = 0; nt < 8; nt++) {
            int c = h * DK_ + nt * 8 + 2 * tg;
            *(uint32_t*)(Xh + ((size_t)(b * S_ + r)) * D_ + c) =
                pack_f16x2(oacc[mt][nt][0] * inv0, oacc[mt][nt][1] * inv0);
            *(uint32_t*)(Xh + ((size_t)(b * S_ + r + 8)) * D_ + c) =
                pack_f16x2(oacc[mt][nt][2] * inv1, oacc[mt][nt][3] * inv1);
        }
    }
}

extern "C" void kernel_launch(void* const* d_in, const int* in_sizes, int n_in,
                              void* d_out, int out_size) {
    (void)in_sizes; (void)n_in; (void)out_size;
    const float* query = (const float*)d_in[0];
    const float* key   = (const float*)d_in[1];
    const float* value = (const float*)d_in[2];
    const int*   mask  = (const int*)d_in[3];
    const float* Wq = (const float*)d_in[4];
    const float* bq = (const float*)d_in[5];
    const float* Wk = (const float*)d_in[6];
    const float* bk = (const float*)d_in[7];
    const float* Wv = (const float*)d_in[8];
    const float* bv = (const float*)d_in[9];
    const float* Wo = (const float*)d_in[10];
    const float* bo = (const float*)d_in[11];
    float* out = (float*)d_out;

    __half *pQh, *pKh, *pVh, *pXh;
    __half *pAq, *pAk, *pAv, *pWq, *pWk, *pWv, *pWo;
    uint32_t* pMb;
    cudaGetSymbolAddress((void**)&pQh, g_Qh);
    cudaGetSymbolAddress((void**)&pKh, g_Kh);
    cudaGetSymbolAddress((void**)&pVh, g_Vh);
    cudaGetSymbolAddress((void**)&pXh, g_Xh);
    cudaGetSymbolAddress((void**)&pAq, g_Ahq);
    cudaGetSymbolAddress((void**)&pAk, g_Ahk);
    cudaGetSymbolAddress((void**)&pAv, g_Ahv);
    cudaGetSymbolAddress((void**)&pWq, g_Whq);
    cudaGetSymbolAddress((void**)&pWk, g_Whk);
    cudaGetSymbolAddress((void**)&pWv, g_Whv);
    cudaGetSymbolAddress((void**)&pWo, g_Who);
    cudaGetSymbolAddress((void**)&pMb, g_Mb);

    static bool attr_done = false;
    if (!attr_done) {
        cudaFuncSetAttribute(gemm3_nt_bias,
                             cudaFuncAttributeMaxDynamicSharedMemorySize, GEMM_SMEM_BYTES);
        cudaFuncSetAttribute(attn_kernel,
                             cudaFuncAttributeMaxDynamicSharedMemorySize, ATTN_SMEM_BYTES);
        attr_done = true;
    }

    const int M = B_ * S_;
    const int NA4 = (B_ * S_ * D_) / 4;
    const int NW4 = (D_ * D_) / 4;

    // One fused prologue launch: 7 fp16 conversions + mask bit-pack.
    prologue_kernel<<<dim3(1024, 8), 256>>>(
        (const float4*)query, (const float4*)key, (const float4*)value,
        (const float4*)Wq, (const float4*)Wk, (const float4*)Wv, (const float4*)Wo,
        pAq, pAk, pAv, pWq, pWk, pWv, pWo, mask, pMb, NA4, NW4);

    // fused QKV projections -> fp16 outputs (Q scaled by log2e/8 in epilogue)
    dim3 gq(D_ / 128, M / 128, 3);
    gemm3_nt_bias<<<gq, 128, GEMM_SMEM_BYTES>>>(
        pAq, pAk, pAv, pWq, pWk, pWv, bq, bk, bv,
        (void*)pQh, (void*)pKh, (void*)pVh, M, D_, D_, 1);

    attn_kernel<<<dim3(H_, S_ / 128, B_), 128, ATTN_SMEM_BYTES>>>(pQh, pKh, pVh, pMb, pXh);

    // output projection (fp16 inputs), fp32 out
    dim3 go(D_ / 128, M / 128, 1);
    gemm3_nt_bias<<<go, 128, GEMM_SMEM_BYTES>>>(
        pXh, pXh, pXh, pWo, pWo, pWo, bo, bo, bo,
        (void*)out, (void*)out, (void*)out, M, D_, D_, 0);
}